// round 5
// baseline (speedup 1.0000x reference)
#include <cuda_runtime.h>

#define NPIX 409600      // 640*640
#define NB   8           // batch
#define MM   16          // max instance ids
#define GRIDX 100        // blocks per batch for the big passes
#define TPB   128
#define ITERS (NPIX / 4 / (GRIDX * TPB))   // = 8 float4-chunks per thread
#define P1STR 81         // pass-1 per-thread histogram stride (coprime with 32 banks)

// ---------------- scratch (device globals; no allocation allowed) ----------
__device__ float g_sums[NB][80];   // [slot*16+bin]: slots 0..3 = sum of sim_j over kern==bin, slot 4 = cnt_k
__device__ float g_lsum[NB][MM];   // segment sums of agg per-pixel loss by text id
__device__ float g_tcnt[NB][MM];   // text pixel counts

// ---------------- kernel 0: zero scratch -----------------------------------
__global__ void k_zero() {
    int i = threadIdx.x;
    if (i < NB * 80) (&g_sums[0][0])[i] = 0.f;
    if (i < NB * MM) {
        (&g_lsum[0][0])[i] = 0.f;
        (&g_tcnt[0][0])[i] = 0.f;
    }
}

// ---------------- kernel 1: kernel-id segment sums --------------------------
// Per-thread privatized shared histogram: 128 threads * 81-float stride (~41.5KB).
// Layout per thread: a[slot*16 + bin], slots 0..3 = Gsum_j, 4 = cnt_k.
__global__ void __launch_bounds__(TPB) k_pass1(const float* __restrict__ preds,
                                               const int* __restrict__ targets) {
    __shared__ float acc[TPB * P1STR];
    const int tid = threadIdx.x;
    const int n   = blockIdx.y;
    float* a = acc + tid * P1STR;
#pragma unroll
    for (int s = 0; s < 80; s++) a[s] = 0.f;

    const float4* c0 = (const float4*)(preds + (size_t)(n * 6 + 2) * NPIX);
    const float4* c1 = (const float4*)(preds + (size_t)(n * 6 + 3) * NPIX);
    const float4* c2 = (const float4*)(preds + (size_t)(n * 6 + 4) * NPIX);
    const float4* c3 = (const float4*)(preds + (size_t)(n * 6 + 5) * NPIX);
    const int4*   kr = (const int4*)(targets + (size_t)(n * 2 + 1) * NPIX);

    const int base = blockIdx.x * TPB + tid;
#pragma unroll 2
    for (int r = 0; r < ITERS; r++) {
        int i = base + r * (GRIDX * TPB);
        float4 s0 = c0[i], s1 = c1[i], s2 = c2[i], s3 = c3[i];
        int4 k4 = kr[i];
        { float* p = a + (k4.x & 15); p[0] += s0.x; p[16] += s1.x; p[32] += s2.x; p[48] += s3.x; p[64] += 1.f; }
        { float* p = a + (k4.y & 15); p[0] += s0.y; p[16] += s1.y; p[32] += s2.y; p[48] += s3.y; p[64] += 1.f; }
        { float* p = a + (k4.z & 15); p[0] += s0.z; p[16] += s1.z; p[32] += s2.z; p[48] += s3.z; p[64] += 1.f; }
        { float* p = a + (k4.w & 15); p[0] += s0.w; p[16] += s1.w; p[32] += s2.w; p[48] += s3.w; p[64] += 1.f; }
    }
    __syncthreads();
    // cross-thread reduce: thread s (<80) sums column s over 128 thread copies
    for (int s = tid; s < 80; s += TPB) {
        float tot = 0.f;
        for (int t = 0; t < TPB; t++) tot += acc[t * P1STR + s];
        atomicAdd(&g_sums[n][s], tot);
    }
}

// ---------------- kernel 2: per-pixel aggregation loss ----------------------
// Computes G means from g_sums at block start (pass1 complete by launch order).
// Per-thread privatized shared: [bin]=lsum, [16+bin]=tcnt, stride 33 (pad).
__global__ void __launch_bounds__(TPB) k_pass2(const float* __restrict__ preds,
                                               const int* __restrict__ targets) {
    __shared__ float Gs[64];            // [bin*4 + j]
    __shared__ float acc[TPB * 33];
    const int tid = threadIdx.x;
    const int n   = blockIdx.y;
    if (tid < 16) {
        float ck  = g_sums[n][64 + tid];
        float inv = 1.f / fmaxf(ck, 1.f);
        Gs[tid * 4 + 0] = g_sums[n][ 0 + tid] * inv;
        Gs[tid * 4 + 1] = g_sums[n][16 + tid] * inv;
        Gs[tid * 4 + 2] = g_sums[n][32 + tid] * inv;
        Gs[tid * 4 + 3] = g_sums[n][48 + tid] * inv;
    }
    float* a = acc + tid * 33;
#pragma unroll
    for (int s = 0; s < 32; s++) a[s] = 0.f;
    __syncthreads();

    const float4* c0 = (const float4*)(preds + (size_t)(n * 6 + 2) * NPIX);
    const float4* c1 = (const float4*)(preds + (size_t)(n * 6 + 3) * NPIX);
    const float4* c2 = (const float4*)(preds + (size_t)(n * 6 + 4) * NPIX);
    const float4* c3 = (const float4*)(preds + (size_t)(n * 6 + 5) * NPIX);
    const int4*   tx = (const int4*)(targets + (size_t)(n * 2) * NPIX);

    const int base = blockIdx.x * TPB + tid;
#pragma unroll 2
    for (int r = 0; r < ITERS; r++) {
        int i = base + r * (GRIDX * TPB);
        float4 s0 = c0[i], s1 = c1[i], s2 = c2[i], s3 = c3[i];
        int4 t4 = tx[i];
#pragma unroll
        for (int p = 0; p < 4; p++) {
            int   t;
            float x0, x1, x2, x3;
            if (p == 0) { t = t4.x & 15; x0 = s0.x; x1 = s1.x; x2 = s2.x; x3 = s3.x; }
            else if (p == 1) { t = t4.y & 15; x0 = s0.y; x1 = s1.y; x2 = s2.y; x3 = s3.y; }
            else if (p == 2) { t = t4.z & 15; x0 = s0.z; x1 = s1.z; x2 = s2.z; x3 = s3.z; }
            else { t = t4.w & 15; x0 = s0.w; x1 = s1.w; x2 = s2.w; x3 = s3.w; }
            float4 g = *(const float4*)&Gs[t * 4];
            float d0 = x0 - g.x, d1 = x1 - g.y, d2 = x2 - g.z, d3 = x3 - g.w;
            float sq = fmaf(d0, d0, fmaf(d1, d1, fmaf(d2, d2, d3 * d3)));
            float nrm;
            asm("sqrt.approx.f32 %0, %1;" : "=f"(nrm) : "f"(sq));
            float d = fmaxf(nrm - 0.5f, 0.f);          // DELTA_AGG = 0.5
            float l = __logf(fmaf(d, d, 1.f));         // log(1)=0 when d<=0
            a[t]      += l;
            a[16 + t] += 1.f;
        }
    }
    __syncthreads();
    for (int s = tid; s < 32; s += TPB) {
        float tot = 0.f;
        for (int t = 0; t < TPB; t++) tot += acc[t * 33 + s];
        if (s < 16) atomicAdd(&g_lsum[n][s], tot);
        else        atomicAdd(&g_tcnt[n][s - 16], tot);
    }
}

// ---------------- kernel 3: finalize agg + dis ------------------------------
// 8 warps; warp n handles batch n.
__global__ void k_final(float* __restrict__ out) {
    const int tid  = threadIdx.x;
    const int n    = tid >> 5;
    const int lane = tid & 31;

    float ck = 0.f, ct = 0.f, ls = 0.f;
    float g0 = 0.f, g1 = 0.f, g2 = 0.f, g3 = 0.f;
    int v = 0;
    if (lane < 16) {
        ck = g_sums[n][64 + lane];
        ct = g_tcnt[n][lane];
        ls = g_lsum[n][lane];
        float inv = 1.f / fmaxf(ck, 1.f);
        g0 = g_sums[n][ 0 + lane] * inv;
        g1 = g_sums[n][16 + lane] * inv;
        g2 = g_sums[n][32 + lane] * inv;
        g3 = g_sums[n][48 + lane] * inv;
        v = (ck > 0.f) && (ct > 0.f) && (lane >= 1);
    }
    unsigned vm = __ballot_sync(0xffffffffu, v);
    int nv = __popc(vm);

    // aggregation: sum over valid of lsum/max(cnt_t,1), divided by max(nv,1)
    float term = v ? ls / fmaxf(ct, 1.f) : 0.f;
#pragma unroll
    for (int o = 16; o; o >>= 1) term += __shfl_down_sync(0xffffffffu, term, o);

    // discrimination: ordered pairs over 16x16, each lane 8 pairs
    float dsum = 0.f;
#pragma unroll
    for (int it = 0; it < 8; it++) {
        int pid = lane + it * 32;
        int m1 = pid >> 4, m2 = pid & 15;
        float a0 = __shfl_sync(0xffffffffu, g0, m1);
        float a1 = __shfl_sync(0xffffffffu, g1, m1);
        float a2 = __shfl_sync(0xffffffffu, g2, m1);
        float a3 = __shfl_sync(0xffffffffu, g3, m1);
        float b0 = __shfl_sync(0xffffffffu, g0, m2);
        float b1 = __shfl_sync(0xffffffffu, g1, m2);
        float b2 = __shfl_sync(0xffffffffu, g2, m2);
        float b3 = __shfl_sync(0xffffffffu, g3, m2);
        if (m1 != m2 && ((vm >> m1) & 1) && ((vm >> m2) & 1)) {
            float e0 = a0 - b0, e1 = a1 - b1, e2 = a2 - b2, e3 = a3 - b3;
            float sq = e0 * e0 + e1 * e1 + e2 * e2 + e3 * e3;
            float dist = sqrtf(sq);
            float dd = fmaxf(3.0f - dist, 0.f);        // DELTA_DIS = 3
            dsum += __logf(fmaf(dd, dd, 1.f));
        }
    }
#pragma unroll
    for (int o = 16; o; o >>= 1) dsum += __shfl_down_sync(0xffffffffu, dsum, o);

    if (lane == 0) {
        out[n] = term / (float)max(nv, 1);
        float dis = 0.f;
        if (nv > 1) dis = 0.5f * dsum / (float)max(nv * (nv - 1), 1);
        out[8 + n] = dis;
    }
}

// ---------------- launch ----------------------------------------------------
extern "C" void kernel_launch(void* const* d_in, const int* in_sizes, int n_in,
                              void* d_out, int out_size) {
    const float* preds   = (const float*)d_in[0];
    const int*   targets = (const int*)d_in[1];
    float*       out     = (float*)d_out;

    k_zero<<<1, 640>>>();
    k_pass1<<<dim3(GRIDX, NB), TPB>>>(preds, targets);
    k_pass2<<<dim3(GRIDX, NB), TPB>>>(preds, targets);
    k_final<<<1, 256>>>(out);
}